// round 2
// baseline (speedup 1.0000x reference)
#include <cuda_runtime.h>
#include <math.h>

#define EPS 1e-5f

// ---------------- scratch (static device globals: no allocation at launch) ----------------
__device__ float g_xA [256*64*64];     // dinormed x            (4 MB)
__device__ float g_g2 [256*128*128];   // guide 2               (16 MB)
__device__ float g_kk1[9*128*128];     // pac1 guide kernels    (0.6 MB)
__device__ float g_xB [128*128*128];   // after pac1            (8 MB)
__device__ float g_g1 [128*256*256];   // guide 1               (32 MB)
__device__ float g_kk2[9*256*256];     // pac2 guide kernels    (2.4 MB)
__device__ float g_xC [64*256*256];    // after pac2            (16 MB)

// ---------------- double instance-norm residual:  z = (x-m)(1+r)(1+r2)+m ----------------
// one block per channel; safe in-place (each element read/written by its owning thread)
__global__ void dinorm_kernel(const float* __restrict__ in, float* __restrict__ out, int N) {
    const int c = blockIdx.x;
    const float* x = in + (size_t)c * N;
    float* y = out + (size_t)c * N;

    float s = 0.f, s2 = 0.f;
    for (int i = threadIdx.x; i < N; i += blockDim.x) {
        float v = x[i];
        s += v; s2 += v * v;
    }
    #pragma unroll
    for (int o = 16; o > 0; o >>= 1) {
        s  += __shfl_down_sync(0xffffffffu, s,  o);
        s2 += __shfl_down_sync(0xffffffffu, s2, o);
    }
    __shared__ float redA[8], redB[8];
    __shared__ float s_m, s_scale;
    int wid = threadIdx.x >> 5, lid = threadIdx.x & 31;
    if (lid == 0) { redA[wid] = s; redB[wid] = s2; }
    __syncthreads();
    if (threadIdx.x == 0) {
        float S = 0.f, S2 = 0.f;
        int nw = blockDim.x >> 5;
        for (int i = 0; i < nw; i++) { S += redA[i]; S2 += redB[i]; }
        float m = S / N;
        float v = S2 / N - m * m;
        if (v < 0.f) v = 0.f;
        float r  = rsqrtf(v + EPS);
        float r2 = rsqrtf(v * (1.f + r) * (1.f + r) + EPS);
        s_m = m; s_scale = (1.f + r) * (1.f + r2);
    }
    __syncthreads();
    float m = s_m, sc = s_scale;
    for (int i = threadIdx.x; i < N; i += blockDim.x) {
        float v = x[i];
        y[i] = (v - m) * sc + m;
    }
}

// ---------------- direct 3x3 SAME conv, NCHW / OIHW ----------------
// tile: 32 wide x 4 high x CO_TILE out channels; thread = (co, 4-pixel strip)
template<int CO_TILE>
__global__ void conv3x3_kernel(const float* __restrict__ in, const float* __restrict__ wt,
                               const float* __restrict__ bias, float* __restrict__ out,
                               int Cin, int H, int W) {
    const int TW = 32, TH = 4, PITCH = 35;
    __shared__ float xs[(TH + 2) * PITCH];
    __shared__ float ws[CO_TILE * 9];

    const int nthr = blockDim.x * blockDim.y * blockDim.z;
    const int tid  = threadIdx.x + blockDim.x * (threadIdx.y + blockDim.y * threadIdx.z);
    const int tx = threadIdx.x;              // 0..7  (4 pixels each)
    const int ty = threadIdx.y;              // 0..3
    const int co = blockIdx.z * CO_TILE + threadIdx.z;
    const int w0 = blockIdx.x * TW;
    const int h0 = blockIdx.y * TH;

    float acc[4] = {0.f, 0.f, 0.f, 0.f};

    for (int ci = 0; ci < Cin; ci++) {
        const float* ip = in + (size_t)ci * H * W;
        for (int idx = tid; idx < (TH + 2) * PITCH; idx += nthr) {
            int r = idx / PITCH, c = idx % PITCH;
            float v = 0.f;
            if (c < TW + 2) {
                int gh = h0 + r - 1, gw = w0 + c - 1;
                if (gh >= 0 && gh < H && gw >= 0 && gw < W) v = ip[gh * W + gw];
            }
            xs[idx] = v;
        }
        for (int idx = tid; idx < CO_TILE * 9; idx += nthr) {
            int cc = idx / 9, t = idx % 9;
            ws[idx] = wt[((size_t)(blockIdx.z * CO_TILE + cc) * Cin + ci) * 9 + t];
        }
        __syncthreads();

        float wr[9];
        #pragma unroll
        for (int t = 0; t < 9; t++) wr[t] = ws[threadIdx.z * 9 + t];

        #pragma unroll
        for (int di = 0; di < 3; di++) {
            float xr[6];
            #pragma unroll
            for (int c = 0; c < 6; c++) xr[c] = xs[(ty + di) * PITCH + tx * 4 + c];
            #pragma unroll
            for (int p = 0; p < 4; p++)
                #pragma unroll
                for (int dj = 0; dj < 3; dj++)
                    acc[p] += xr[p + dj] * wr[di * 3 + dj];
        }
        __syncthreads();
    }

    int gh = h0 + ty;
    if (gh < H) {
        float bv = bias[co];
        #pragma unroll
        for (int p = 0; p < 4; p++) {
            int gw = w0 + tx * 4 + p;
            if (gw < W) out[((size_t)co * H + gh) * W + gw] = acc[p] + bv;
        }
    }
}

// ---------------- guide kernel:  kk[t][h][w] = exp(-0.5 * sum_c (g_pad[h+di-1][w+dj-1]-g[h][w])^2) ----------------
__global__ void kk_kernel(const float* __restrict__ g, float* __restrict__ kk,
                          int Cg, int H, int W) {
    const int T = 16, PITCH = T + 2;
    __shared__ float gs[PITCH * PITCH];
    const int w0 = blockIdx.x * T, h0 = blockIdx.y * T;
    const int tx = threadIdx.x % T, ty = threadIdx.x / T;

    float acc[9];
    #pragma unroll
    for (int t = 0; t < 9; t++) acc[t] = 0.f;

    for (int c = 0; c < Cg; c++) {
        const float* gp = g + (size_t)c * H * W;
        for (int idx = threadIdx.x; idx < PITCH * PITCH; idx += 256) {
            int r = idx / PITCH, cc = idx % PITCH;
            int gh = h0 + r - 1, gw = w0 + cc - 1;
            gs[idx] = (gh >= 0 && gh < H && gw >= 0 && gw < W) ? gp[gh * W + gw] : 0.f;
        }
        __syncthreads();
        float ctr = gs[(ty + 1) * PITCH + tx + 1];
        #pragma unroll
        for (int di = 0; di < 3; di++)
            #pragma unroll
            for (int dj = 0; dj < 3; dj++) {
                float d = gs[(ty + di) * PITCH + tx + dj] - ctr;
                acc[di * 3 + dj] += d * d;
            }
        __syncthreads();
    }
    int gh = h0 + ty, gw = w0 + tx;
    #pragma unroll
    for (int t = 0; t < 9; t++)
        kk[((size_t)t * H + gh) * W + gw] = expf(-0.5f * acc[t]);
}

// ---------------- PAC transposed conv (stride 2, pad 1, out_pad 1, k=3) ----------------
// parity structure: a 2x2 output quad at (2r..2r+1, 2s..2s+1) reads the 2x2 input
// cell x[r..r+1][s..s+1] through exactly the 9 weight taps (one (pixel,tap) pair each).
// Accumulate the 9 pairs over Cin in regs, apply kk + bias in epilogue.
// x: (Cin,H,W)  kk: (9,2H,2W)  wt: (Cin,Cout,3,3)  out: (Cout,2H,2W)
__global__ void pac_kernel(const float* __restrict__ x, const float* __restrict__ kk,
                           const float* __restrict__ wt, const float* __restrict__ bias,
                           float* __restrict__ out, int Cin, int Cout, int H, int W) {
    const int PITCH = 33;                       // 32 quads wide -> 33 x cols
    __shared__ float xs[9 * PITCH];             // 9 x rows (8 quad rows + 1)
    __shared__ float ws[4 * 9];
    const int tid = threadIdx.x;                // 256 threads
    const int tx = tid & 7, ty = (tid >> 3) & 7, tz = tid >> 6;
    const int s0 = blockIdx.x * 32, r0 = blockIdx.y * 8;
    const int co = blockIdx.z * 4 + tz;

    float acc[4][9];
    #pragma unroll
    for (int q = 0; q < 4; q++)
        #pragma unroll
        for (int p = 0; p < 9; p++) acc[q][p] = 0.f;

    for (int ci = 0; ci < Cin; ci++) {
        const float* ip = x + (size_t)ci * H * W;
        for (int idx = tid; idx < 9 * PITCH; idx += 256) {
            int r = idx / PITCH, c = idx % PITCH;
            int gr = r0 + r, gs_ = s0 + c;
            xs[idx] = (gr < H && gs_ < W) ? ip[gr * W + gs_] : 0.f;
        }
        if (tid < 36) {
            int cc = tid / 9, t = tid % 9;
            ws[tid] = wt[((size_t)ci * Cout + blockIdx.z * 4 + cc) * 9 + t];
        }
        __syncthreads();

        float wr[9];
        #pragma unroll
        for (int t = 0; t < 9; t++) wr[t] = ws[tz * 9 + t];
        float xa[5], xb[5];
        #pragma unroll
        for (int k = 0; k < 5; k++) {
            xa[k] = xs[ty * PITCH + tx * 4 + k];
            xb[k] = xs[(ty + 1) * PITCH + tx * 4 + k];
        }
        #pragma unroll
        for (int q = 0; q < 4; q++) {
            float x00 = xa[q], x01 = xa[q + 1], x10 = xb[q], x11 = xb[q + 1];
            acc[q][0] += x00 * wr[4];   // out(2r,2s)       tap(1,1)
            acc[q][1] += x00 * wr[3];   // out(2r,2s+1)     tap(1,0)
            acc[q][2] += x01 * wr[5];   // out(2r,2s+1)     tap(1,2)
            acc[q][3] += x00 * wr[1];   // out(2r+1,2s)     tap(0,1)
            acc[q][4] += x10 * wr[7];   // out(2r+1,2s)     tap(2,1)
            acc[q][5] += x00 * wr[0];   // out(2r+1,2s+1)   tap(0,0)
            acc[q][6] += x01 * wr[2];   // out(2r+1,2s+1)   tap(0,2)
            acc[q][7] += x10 * wr[6];   // out(2r+1,2s+1)   tap(2,0)
            acc[q][8] += x11 * wr[8];   // out(2r+1,2s+1)   tap(2,2)
        }
        __syncthreads();
    }

    const int Ho = 2 * H, Wo = 2 * W;
    const size_t HW = (size_t)Ho * Wo;
    float bv = bias[co];
    int r = r0 + ty;
    float* op = out + (size_t)co * HW;
    #pragma unroll
    for (int q = 0; q < 4; q++) {
        int s = s0 + tx * 4 + q;
        size_t b00 = (size_t)(2 * r) * Wo + 2 * s;
        size_t b10 = b00 + Wo;
        float o00 = bv + kk[4 * HW + b00] * acc[q][0];
        float o01 = bv + kk[3 * HW + b00 + 1] * acc[q][1]
                       + kk[5 * HW + b00 + 1] * acc[q][2];
        float o10 = bv + kk[1 * HW + b10] * acc[q][3]
                       + kk[7 * HW + b10] * acc[q][4];
        float o11 = bv + kk[0 * HW + b10 + 1] * acc[q][5]
                       + kk[2 * HW + b10 + 1] * acc[q][6]
                       + kk[6 * HW + b10 + 1] * acc[q][7]
                       + kk[8 * HW + b10 + 1] * acc[q][8];
        op[b00] = o00; op[b00 + 1] = o01;
        op[b10] = o10; op[b10 + 1] = o11;
    }
}

// ---------------- launch ----------------
extern "C" void kernel_launch(void* const* d_in, const int* in_sizes, int n_in,
                              void* d_out, int out_size) {
    const float* x       = (const float*)d_in[0];
    const float* ef_lv2  = (const float*)d_in[1];
    const float* ef_lv1  = (const float*)d_in[2];
    const float* w_adj2  = (const float*)d_in[3];
    const float* b_adj2  = (const float*)d_in[4];
    const float* w_adj1  = (const float*)d_in[5];
    const float* b_adj1  = (const float*)d_in[6];
    const float* w_pac16 = (const float*)d_in[7];
    const float* b_pac16 = (const float*)d_in[8];
    const float* w_pac20 = (const float*)d_in[9];
    const float* b_pac20 = (const float*)d_in[10];
    const float* w_out   = (const float*)d_in[11];
    const float* b_out   = (const float*)d_in[12];
    float* outp = (float*)d_out;

    float *xA, *g2, *kk1, *xB, *g1, *kk2, *xC;
    cudaGetSymbolAddress((void**)&xA,  g_xA);
    cudaGetSymbolAddress((void**)&g2,  g_g2);
    cudaGetSymbolAddress((void**)&kk1, g_kk1);
    cudaGetSymbolAddress((void**)&xB,  g_xB);
    cudaGetSymbolAddress((void**)&g1,  g_g1);
    cudaGetSymbolAddress((void**)&kk2, g_kk2);
    cudaGetSymbolAddress((void**)&xC,  g_xC);

    // stage 1: x = inorm(inorm(x)+x)+inorm(x)+x   (collapsed)   (256,64,64)
    dinorm_kernel<<<256, 256>>>(x, xA, 64 * 64);

    // g2 = conv3x3(ef_lv2; 128->256 @128x128)
    conv3x3_kernel<8><<<dim3(4, 32, 32), dim3(8, 4, 8)>>>(ef_lv2, w_adj2, b_adj2, g2, 128, 128, 128);

    // kk1 from g2 (Cg=256 @128x128)
    kk_kernel<<<dim3(8, 8), 256>>>(g2, kk1, 256, 128, 128);

    // pac1: (256,64,64) -> (128,128,128)
    pac_kernel<<<dim3(2, 8, 32), 256>>>(xA, kk1, w_pac16, b_pac16, xB, 256, 128, 64, 64);

    // double inorm residual on xB (128,128,128), in place
    dinorm_kernel<<<128, 256>>>(xB, xB, 128 * 128);

    // g1 = conv3x3(ef_lv1; 64->128 @256x256)
    conv3x3_kernel<8><<<dim3(8, 64, 16), dim3(8, 4, 8)>>>(ef_lv1, w_adj1, b_adj1, g1, 64, 256, 256);

    // kk2 from g1 (Cg=128 @256x256)
    kk_kernel<<<dim3(16, 16), 256>>>(g1, kk2, 128, 256, 256);

    // pac2: (128,128,128) -> (64,256,256)
    pac_kernel<<<dim3(4, 16, 16), 256>>>(xB, kk2, w_pac20, b_pac20, xC, 128, 64, 128, 128);

    // double inorm residual on xC (64,256,256), in place
    dinorm_kernel<<<64, 256>>>(xC, xC, 256 * 256);

    // final conv: 64->3 @256x256
    conv3x3_kernel<3><<<dim3(8, 64, 1), dim3(8, 4, 3)>>>(xC, w_out, b_out, outp, 64, 256, 256);
}

// round 4
// speedup vs baseline: 1.8003x; 1.8003x over previous
#include <cuda_runtime.h>
#include <cuda_bf16.h>
#include <math.h>
#include <cstdint>

#define EPS 1e-5f

// ---------------- scratch (static device globals) ----------------
__device__ float g_xA [256*64*64];
__device__ float g_g2 [256*128*128];
__device__ float g_kk1[9*128*128];
__device__ float g_xB [128*128*128];
__device__ float g_g1 [128*256*256];
__device__ float g_kk2[9*256*256];
__device__ float g_xC [64*256*256];

// ---------------- double instance-norm residual ----------------
__global__ void dinorm_kernel(const float* __restrict__ in, float* __restrict__ out, int N) {
    const int c = blockIdx.x;
    const float* x = in + (size_t)c * N;
    float* y = out + (size_t)c * N;

    float s = 0.f, s2 = 0.f;
    for (int i = threadIdx.x; i < N; i += blockDim.x) {
        float v = x[i];
        s += v; s2 += v * v;
    }
    #pragma unroll
    for (int o = 16; o > 0; o >>= 1) {
        s  += __shfl_down_sync(0xffffffffu, s,  o);
        s2 += __shfl_down_sync(0xffffffffu, s2, o);
    }
    __shared__ float redA[8], redB[8];
    __shared__ float s_m, s_scale;
    int wid = threadIdx.x >> 5, lid = threadIdx.x & 31;
    if (lid == 0) { redA[wid] = s; redB[wid] = s2; }
    __syncthreads();
    if (threadIdx.x == 0) {
        float S = 0.f, S2 = 0.f;
        int nw = blockDim.x >> 5;
        for (int i = 0; i < nw; i++) { S += redA[i]; S2 += redB[i]; }
        float m = S / N;
        float v = S2 / N - m * m;
        if (v < 0.f) v = 0.f;
        float r  = rsqrtf(v + EPS);
        float r2 = rsqrtf(v * (1.f + r) * (1.f + r) + EPS);
        s_m = m; s_scale = (1.f + r) * (1.f + r2);
    }
    __syncthreads();
    float m = s_m, sc = s_scale;
    for (int i = threadIdx.x; i < N; i += blockDim.x) {
        float v = x[i];
        y[i] = (v - m) * sc + m;
    }
}

// ---------------- bf16 mma.sync implicit-GEMM 3x3 SAME conv ----------------
// D[px][co] = sum_k A[px][k] * B[co][k],  k = ci*9 + tap,  K = Cin*9 (mult of 64)
// Block: M=128 px (one image-row strip) x N=128 co. 8 warps = 4(M) x 2(N),
// warp tile 32x64 via mma.sync.m16n8k16.bf16 (base ISA, no arch-a features).
__device__ __forceinline__ void mma_bf16(float* c, uint32_t a0, uint32_t a1,
                                         uint32_t a2, uint32_t a3,
                                         uint32_t b0, uint32_t b1) {
    asm volatile(
        "mma.sync.aligned.m16n8k16.row.col.f32.bf16.bf16.f32 "
        "{%0,%1,%2,%3}, {%4,%5,%6,%7}, {%8,%9}, {%0,%1,%2,%3};"
        : "+f"(c[0]), "+f"(c[1]), "+f"(c[2]), "+f"(c[3])
        : "r"(a0), "r"(a1), "r"(a2), "r"(a3), "r"(b0), "r"(b1));
}

__global__ __launch_bounds__(256) void conv_mma_kernel(
    const float* __restrict__ in, const float* __restrict__ wt,
    const float* __restrict__ bias, float* __restrict__ out,
    int Cin, int H, int W, int co0)
{
    const int PITCH = 36;                       // u32 pitch: banks 4r+c -> conflict-free frags
    __shared__ uint32_t xs[128 * PITCH];        // A: [px][kpair] bf16x2
    __shared__ uint32_t ws[128 * PITCH];        // B: [co][kpair] bf16x2

    const int tid = threadIdx.x, wid = tid >> 5, lane = tid & 31;
    const int h = blockIdx.y, col0 = blockIdx.x * 128;
    const size_t HW = (size_t)H * W;
    const int K = Cin * 9;
    const int nch = K / 64;

    const int wm = wid & 3, wn = wid >> 2;
    const int m0 = wm * 32, n0 = wn * 64;

    float acc[2][8][4];
    #pragma unroll
    for (int mt = 0; mt < 2; mt++)
        #pragma unroll
        for (int nt = 0; nt < 8; nt++)
            #pragma unroll
            for (int r = 0; r < 4; r++) acc[mt][nt][r] = 0.f;

    for (int ch = 0; ch < nch; ch++) {
        const int k0 = ch * 64;

        // ---- stage A: 128 px x 32 kpairs ----
        #pragma unroll
        for (int e = 0; e < 4; e++) {
            int kp = wid * 4 + e;
            int k  = k0 + kp * 2;
            int ci0 = k / 9, t0 = k - ci0 * 9;
            int di0 = t0 / 3, dj0 = t0 - di0 * 3;
            int k1 = k + 1;
            int ci1 = k1 / 9, t1 = k1 - ci1 * 9;
            int di1 = t1 / 3, dj1 = t1 - di1 * 3;
            int gh0 = h + di0 - 1, gh1 = h + di1 - 1;
            bool ok0 = (gh0 >= 0 && gh0 < H), ok1 = (gh1 >= 0 && gh1 < H);
            const float* ip0 = in + (size_t)ci0 * HW + (size_t)gh0 * W;
            const float* ip1 = in + (size_t)ci1 * HW + (size_t)gh1 * W;
            #pragma unroll
            for (int p4 = 0; p4 < 4; p4++) {
                int px = p4 * 32 + lane;
                int gw0 = col0 + px + dj0 - 1;
                int gw1 = col0 + px + dj1 - 1;
                float v0 = (ok0 && gw0 >= 0 && gw0 < W) ? ip0[gw0] : 0.f;
                float v1 = (ok1 && gw1 >= 0 && gw1 < W) ? ip1[gw1] : 0.f;
                __nv_bfloat162 pk = __floats2bfloat162_rn(v0, v1);
                xs[px * PITCH + kp] = *reinterpret_cast<uint32_t*>(&pk);
            }
        }
        // ---- stage B: 128 co x 32 kpairs ----
        #pragma unroll
        for (int i = 0; i < 16; i++) {
            int n = wid + 8 * i;
            const float* wp = wt + (size_t)(co0 + n) * K + k0 + 2 * lane;
            __nv_bfloat162 pk = __floats2bfloat162_rn(wp[0], wp[1]);
            ws[n * PITCH + lane] = *reinterpret_cast<uint32_t*>(&pk);
        }
        __syncthreads();

        // ---- compute: 4 k16-steps ----
        #pragma unroll
        for (int ks = 0; ks < 4; ks++) {
            int ar = lane >> 2, ac = ks * 8 + (lane & 3);
            uint32_t a[2][4];
            #pragma unroll
            for (int mt = 0; mt < 2; mt++) {
                int r = m0 + mt * 16 + ar;
                a[mt][0] = xs[r * PITCH + ac];
                a[mt][1] = xs[(r + 8) * PITCH + ac];
                a[mt][2] = xs[r * PITCH + ac + 4];
                a[mt][3] = xs[(r + 8) * PITCH + ac + 4];
            }
            #pragma unroll
            for (int nt = 0; nt < 8; nt++) {
                int n = n0 + nt * 8 + ar;
                uint32_t b0 = ws[n * PITCH + ac];
                uint32_t b1 = ws[n * PITCH + ac + 4];
                mma_bf16(acc[0][nt], a[0][0], a[0][1], a[0][2], a[0][3], b0, b1);
                mma_bf16(acc[1][nt], a[1][0], a[1][1], a[1][2], a[1][3], b0, b1);
            }
        }
        __syncthreads();
    }

    // ---- epilogue ----
    #pragma unroll
    for (int nt = 0; nt < 8; nt++) {
        int co = co0 + n0 + nt * 8 + 2 * (lane & 3);
        float bv0 = bias[co], bv1 = bias[co + 1];
        float* o0 = out + (size_t)co * HW + (size_t)h * W;
        float* o1 = out + (size_t)(co + 1) * HW + (size_t)h * W;
        #pragma unroll
        for (int mt = 0; mt < 2; mt++) {
            int px = col0 + m0 + mt * 16 + (lane >> 2);
            o0[px]     = acc[mt][nt][0] + bv0;
            o1[px]     = acc[mt][nt][1] + bv1;
            o0[px + 8] = acc[mt][nt][2] + bv0;
            o1[px + 8] = acc[mt][nt][3] + bv1;
        }
    }
}

// ---------------- scalar 3x3 conv (final 64->3 only) ----------------
template<int CO_TILE>
__global__ void conv3x3_kernel(const float* __restrict__ in, const float* __restrict__ wt,
                               const float* __restrict__ bias, float* __restrict__ out,
                               int Cin, int H, int W) {
    const int TW = 32, TH = 4, PITCH = 35;
    __shared__ float xs[(TH + 2) * PITCH];
    __shared__ float ws[CO_TILE * 9];

    const int nthr = blockDim.x * blockDim.y * blockDim.z;
    const int tid  = threadIdx.x + blockDim.x * (threadIdx.y + blockDim.y * threadIdx.z);
    const int tx = threadIdx.x;
    const int ty = threadIdx.y;
    const int co = blockIdx.z * CO_TILE + threadIdx.z;
    const int w0 = blockIdx.x * TW;
    const int h0 = blockIdx.y * TH;

    float acc[4] = {0.f, 0.f, 0.f, 0.f};

    for (int ci = 0; ci < Cin; ci++) {
        const float* ip = in + (size_t)ci * H * W;
        for (int idx = tid; idx < (TH + 2) * PITCH; idx += nthr) {
            int r = idx / PITCH, c = idx % PITCH;
            float v = 0.f;
            if (c < TW + 2) {
                int gh = h0 + r - 1, gw = w0 + c - 1;
                if (gh >= 0 && gh < H && gw >= 0 && gw < W) v = ip[gh * W + gw];
            }
            xs[idx] = v;
        }
        for (int idx = tid; idx < CO_TILE * 9; idx += nthr) {
            int cc = idx / 9, t = idx % 9;
            ws[idx] = wt[((size_t)(blockIdx.z * CO_TILE + cc) * Cin + ci) * 9 + t];
        }
        __syncthreads();

        float wr[9];
        #pragma unroll
        for (int t = 0; t < 9; t++) wr[t] = ws[threadIdx.z * 9 + t];

        #pragma unroll
        for (int di = 0; di < 3; di++) {
            float xr[6];
            #pragma unroll
            for (int c = 0; c < 6; c++) xr[c] = xs[(ty + di) * PITCH + tx * 4 + c];
            #pragma unroll
            for (int p = 0; p < 4; p++)
                #pragma unroll
                for (int dj = 0; dj < 3; dj++)
                    acc[p] += xr[p + dj] * wr[di * 3 + dj];
        }
        __syncthreads();
    }

    int gh = h0 + ty;
    if (gh < H) {
        float bv = bias[co];
        #pragma unroll
        for (int p = 0; p < 4; p++) {
            int gw = w0 + tx * 4 + p;
            if (gw < W) out[((size_t)co * H + gh) * W + gw] = acc[p] + bv;
        }
    }
}

// ---------------- guide kernel ----------------
__global__ void kk_kernel(const float* __restrict__ g, float* __restrict__ kk,
                          int Cg, int H, int W) {
    const int T = 16, PITCH = T + 2;
    __shared__ float gs[PITCH * PITCH];
    const int w0 = blockIdx.x * T, h0 = blockIdx.y * T;
    const int tx = threadIdx.x % T, ty = threadIdx.x / T;

    float acc[9];
    #pragma unroll
    for (int t = 0; t < 9; t++) acc[t] = 0.f;

    for (int c = 0; c < Cg; c++) {
        const float* gp = g + (size_t)c * H * W;
        for (int idx = threadIdx.x; idx < PITCH * PITCH; idx += 256) {
            int r = idx / PITCH, cc = idx % PITCH;
            int gh = h0 + r - 1, gw = w0 + cc - 1;
            gs[idx] = (gh >= 0 && gh < H && gw >= 0 && gw < W) ? gp[gh * W + gw] : 0.f;
        }
        __syncthreads();
        float ctr = gs[(ty + 1) * PITCH + tx + 1];
        #pragma unroll
        for (int di = 0; di < 3; di++)
            #pragma unroll
            for (int dj = 0; dj < 3; dj++) {
                float d = gs[(ty + di) * PITCH + tx + dj] - ctr;
                acc[di * 3 + dj] += d * d;
            }
        __syncthreads();
    }
    int gh = h0 + ty, gw = w0 + tx;
    #pragma unroll
    for (int t = 0; t < 9; t++)
        kk[((size_t)t * H + gh) * W + gw] = expf(-0.5f * acc[t]);
}

// ---------------- PAC transposed conv (stride 2, parity-sparse), CI_TILE=4 ----------------
__global__ __launch_bounds__(256) void pac_kernel(
    const float* __restrict__ x, const float* __restrict__ kk,
    const float* __restrict__ wt, const float* __restrict__ bias,
    float* __restrict__ out, int Cin, int Cout, int H, int W)
{
    __shared__ float xs[4][9 * 36];
    __shared__ float ws[4][4 * 12];
    const int tid = threadIdx.x;
    const int tx = tid & 7, ty = (tid >> 3) & 7, tz = tid >> 6;
    const int s0 = blockIdx.x * 32, r0 = blockIdx.y * 8;
    const int coBase = blockIdx.z * 4;
    const int co = coBase + tz;

    float acc[4][9];
    #pragma unroll
    for (int q = 0; q < 4; q++)
        #pragma unroll
        for (int p = 0; p < 9; p++) acc[q][p] = 0.f;

    for (int cb = 0; cb < Cin; cb += 4) {
        #pragma unroll
        for (int ci4 = 0; ci4 < 4; ci4++) {
            const float* ip = x + (size_t)(cb + ci4) * H * W;
            for (int idx = tid; idx < 9 * 33; idx += 256) {
                int r = idx / 33, c = idx - r * 33;
                int gr = r0 + r, gc = s0 + c;
                xs[ci4][r * 36 + c] = (gr < H && gc < W) ? ip[gr * W + gc] : 0.f;
            }
        }
        if (tid < 144) {
            int ci4 = tid / 36, rem = tid - ci4 * 36, cc = rem / 9, t = rem - cc * 9;
            ws[ci4][cc * 12 + t] = wt[((size_t)(cb + ci4) * Cout + coBase + cc) * 9 + t];
        }
        __syncthreads();

        #pragma unroll
        for (int ci4 = 0; ci4 < 4; ci4++) {
            float4 w0v = *(const float4*)&ws[ci4][tz * 12];
            float4 w1v = *(const float4*)&ws[ci4][tz * 12 + 4];
            float  w8  = ws[ci4][tz * 12 + 8];
            float wr[9] = {w0v.x, w0v.y, w0v.z, w0v.w, w1v.x, w1v.y, w1v.z, w1v.w, w8};
            float4 a4 = *(const float4*)&xs[ci4][ty * 36 + tx * 4];
            float  a5 = xs[ci4][ty * 36 + tx * 4 + 4];
            float4 b4 = *(const float4*)&xs[ci4][(ty + 1) * 36 + tx * 4];
            float  b5 = xs[ci4][(ty + 1) * 36 + tx * 4 + 4];
            float xa[5] = {a4.x, a4.y, a4.z, a4.w, a5};
            float xb[5] = {b4.x, b4.y, b4.z, b4.w, b5};
            #pragma unroll
            for (int q = 0; q < 4; q++) {
                float x00 = xa[q], x01 = xa[q + 1], x10 = xb[q], x11 = xb[q + 1];
                acc[q][0] += x00 * wr[4];
                acc[q][1] += x00 * wr[3];
                acc[q][2] += x01 * wr[5];
                acc[q][3] += x00 * wr[1];
                acc[q][4] += x10 * wr[7];
                acc[q][5] += x00 * wr[0];
                acc[q][6] += x01 * wr[2];
                acc[q][7] += x10 * wr[6];
                acc[q][8] += x11 * wr[8];
            }
        }
        __syncthreads();
    }

    const int Ho = 2 * H, Wo = 2 * W;
    const size_t HW = (size_t)Ho * Wo;
    float bv = bias[co];
    int r = r0 + ty;
    float* op = out + (size_t)co * HW;
    #pragma unroll
    for (int q = 0; q < 4; q++) {
        int s = s0 + tx * 4 + q;
        size_t b00 = (size_t)(2 * r) * Wo + 2 * s;
        size_t b10 = b00 + Wo;
        float o00 = bv + kk[4 * HW + b00] * acc[q][0];
        float o01 = bv + kk[3 * HW + b00 + 1] * acc[q][1]
                       + kk[5 * HW + b00 + 1] * acc[q][2];
        float o10 = bv + kk[1 * HW + b10] * acc[q][3]
                       + kk[7 * HW + b10] * acc[q][4];
        float o11 = bv + kk[0 * HW + b10 + 1] * acc[q][5]
                       + kk[2 * HW + b10 + 1] * acc[q][6]
                       + kk[6 * HW + b10 + 1] * acc[q][7]
                       + kk[8 * HW + b10 + 1] * acc[q][8];
        op[b00] = o00; op[b00 + 1] = o01;
        op[b10] = o10; op[b10 + 1] = o11;
    }
}

// ---------------- launch ----------------
extern "C" void kernel_launch(void* const* d_in, const int* in_sizes, int n_in,
                              void* d_out, int out_size) {
    const float* x       = (const float*)d_in[0];
    const float* ef_lv2  = (const float*)d_in[1];
    const float* ef_lv1  = (const float*)d_in[2];
    const float* w_adj2  = (const float*)d_in[3];
    const float* b_adj2  = (const float*)d_in[4];
    const float* w_adj1  = (const float*)d_in[5];
    const float* b_adj1  = (const float*)d_in[6];
    const float* w_pac16 = (const float*)d_in[7];
    const float* b_pac16 = (const float*)d_in[8];
    const float* w_pac20 = (const float*)d_in[9];
    const float* b_pac20 = (const float*)d_in[10];
    const float* w_out   = (const float*)d_in[11];
    const float* b_out   = (const float*)d_in[12];
    float* outp = (float*)d_out;

    float *xA, *g2, *kk1, *xB, *g1, *kk2, *xC;
    cudaGetSymbolAddress((void**)&xA,  g_xA);
    cudaGetSymbolAddress((void**)&g2,  g_g2);
    cudaGetSymbolAddress((void**)&kk1, g_kk1);
    cudaGetSymbolAddress((void**)&xB,  g_xB);
    cudaGetSymbolAddress((void**)&g1,  g_g1);
    cudaGetSymbolAddress((void**)&kk2, g_kk2);
    cudaGetSymbolAddress((void**)&xC,  g_xC);

    // stage 1: collapsed double inorm-residual (256, 64, 64)
    dinorm_kernel<<<256, 256>>>(x, xA, 64 * 64);

    // g2 = conv3x3(ef_lv2; 128->256 @128x128): K = 1152, N split in two 128-halves
    conv_mma_kernel<<<dim3(1, 128, 1), 256>>>(ef_lv2, w_adj2, b_adj2, g2, 128, 128, 128, 0);
    conv_mma_kernel<<<dim3(1, 128, 1), 256>>>(ef_lv2, w_adj2, b_adj2, g2, 128, 128, 128, 128);

    // kk1 from g2
    kk_kernel<<<dim3(8, 8), 256>>>(g2, kk1, 256, 128, 128);

    // pac1: (256,64,64) -> (128,128,128)
    pac_kernel<<<dim3(2, 8, 32), 256>>>(xA, kk1, w_pac16, b_pac16, xB, 256, 128, 64, 64);

    dinorm_kernel<<<128, 256>>>(xB, xB, 128 * 128);

    // g1 = conv3x3(ef_lv1; 64->128 @256x256): K = 576
    conv_mma_kernel<<<dim3(2, 256, 1), 256>>>(ef_lv1, w_adj1, b_adj1, g1, 64, 256, 256, 0);

    // kk2 from g1
    kk_kernel<<<dim3(16, 16), 256>>>(g1, kk2, 128, 256, 256);

    // pac2: (128,128,128) -> (64,256,256)
    pac_kernel<<<dim3(4, 16, 16), 256>>>(xB, kk2, w_pac20, b_pac20, xC, 128, 64, 128, 128);

    dinorm_kernel<<<64, 256>>>(xC, xC, 256 * 256);

    // final conv: 64->3 @256x256 (scalar fp32, precision-critical path)
    conv3x3_kernel<3><<<dim3(8, 64, 1), dim3(8, 4, 3)>>>(xC, w_out, b_out, outp, 64, 256, 256);
}

// round 8
// speedup vs baseline: 2.1402x; 1.1888x over previous
#include <cuda_runtime.h>
#include <cuda_bf16.h>
#include <math.h>
#include <cstdint>

#define EPS 1e-5f

// ---------------- scratch (static device globals) ----------------
__device__ float g_xA [256*64*64];
__device__ float g_g2 [256*128*128];
__device__ float g_kk1[9*128*128];
__device__ float g_xB [128*128*128];
__device__ float g_g1 [128*256*256];
__device__ float g_kk2[9*256*256];
__device__ float g_xC [64*256*256];

// ---------------- double instance-norm residual ----------------
__global__ void dinorm_kernel(const float* __restrict__ in, float* __restrict__ out, int N) {
    const int c = blockIdx.x;
    const float* x = in + (size_t)c * N;
    float* y = out + (size_t)c * N;

    float s = 0.f, s2 = 0.f;
    for (int i = threadIdx.x; i < N; i += blockDim.x) {
        float v = x[i];
        s += v; s2 += v * v;
    }
    #pragma unroll
    for (int o = 16; o > 0; o >>= 1) {
        s  += __shfl_down_sync(0xffffffffu, s,  o);
        s2 += __shfl_down_sync(0xffffffffu, s2, o);
    }
    __shared__ float redA[8], redB[8];
    __shared__ float s_m, s_scale;
    int wid = threadIdx.x >> 5, lid = threadIdx.x & 31;
    if (lid == 0) { redA[wid] = s; redB[wid] = s2; }
    __syncthreads();
    if (threadIdx.x == 0) {
        float S = 0.f, S2 = 0.f;
        int nw = blockDim.x >> 5;
        for (int i = 0; i < nw; i++) { S += redA[i]; S2 += redB[i]; }
        float m = S / N;
        float v = S2 / N - m * m;
        if (v < 0.f) v = 0.f;
        float r  = rsqrtf(v + EPS);
        float r2 = rsqrtf(v * (1.f + r) * (1.f + r) + EPS);
        s_m = m; s_scale = (1.f + r) * (1.f + r2);
    }
    __syncthreads();
    float m = s_m, sc = s_scale;
    for (int i = threadIdx.x; i < N; i += blockDim.x) {
        float v = x[i];
        y[i] = (v - m) * sc + m;
    }
}

// ---------------- bf16 mma.sync implicit-GEMM 3x3 SAME conv ----------------
__device__ __forceinline__ void mma_bf16(float* c, uint32_t a0, uint32_t a1,
                                         uint32_t a2, uint32_t a3,
                                         uint32_t b0, uint32_t b1) {
    asm volatile(
        "mma.sync.aligned.m16n8k16.row.col.f32.bf16.bf16.f32 "
        "{%0,%1,%2,%3}, {%4,%5,%6,%7}, {%8,%9}, {%0,%1,%2,%3};"
        : "+f"(c[0]), "+f"(c[1]), "+f"(c[2]), "+f"(c[3])
        : "r"(a0), "r"(a1), "r"(a2), "r"(a3), "r"(b0), "r"(b1));
}

__global__ __launch_bounds__(256) void conv_mma_kernel(
    const float* __restrict__ in, const float* __restrict__ wt,
    const float* __restrict__ bias, float* __restrict__ out,
    int Cin, int H, int W)
{
    const int PITCH = 36;
    __shared__ uint32_t xs[128 * PITCH];
    __shared__ uint32_t ws[128 * PITCH];

    const int tid = threadIdx.x, wid = tid >> 5, lane = tid & 31;
    const int h = blockIdx.y, col0 = blockIdx.x * 128;
    const int co0 = blockIdx.z * 128;
    const size_t HW = (size_t)H * W;
    const int K = Cin * 9;
    const int nch = K / 64;

    const int wm = wid & 3, wn = wid >> 2;
    const int m0 = wm * 32, n0 = wn * 64;

    float acc[2][8][4];
    #pragma unroll
    for (int mt = 0; mt < 2; mt++)
        #pragma unroll
        for (int nt = 0; nt < 8; nt++)
            #pragma unroll
            for (int r = 0; r < 4; r++) acc[mt][nt][r] = 0.f;

    for (int ch = 0; ch < nch; ch++) {
        const int k0 = ch * 64;

        #pragma unroll
        for (int e = 0; e < 4; e++) {
            int kp = wid * 4 + e;
            int k  = k0 + kp * 2;
            int ci0 = k / 9, t0 = k - ci0 * 9;
            int di0 = t0 / 3, dj0 = t0 - di0 * 3;
            int k1 = k + 1;
            int ci1 = k1 / 9, t1 = k1 - ci1 * 9;
            int di1 = t1 / 3, dj1 = t1 - di1 * 3;
            int gh0 = h + di0 - 1, gh1 = h + di1 - 1;
            bool ok0 = (gh0 >= 0 && gh0 < H), ok1 = (gh1 >= 0 && gh1 < H);
            const float* ip0 = in + (size_t)ci0 * HW + (size_t)gh0 * W;
            const float* ip1 = in + (size_t)ci1 * HW + (size_t)gh1 * W;
            #pragma unroll
            for (int p4 = 0; p4 < 4; p4++) {
                int px = p4 * 32 + lane;
                int gw0 = col0 + px + dj0 - 1;
                int gw1 = col0 + px + dj1 - 1;
                float v0 = (ok0 && gw0 >= 0 && gw0 < W) ? ip0[gw0] : 0.f;
                float v1 = (ok1 && gw1 >= 0 && gw1 < W) ? ip1[gw1] : 0.f;
                __nv_bfloat162 pk = __floats2bfloat162_rn(v0, v1);
                xs[px * PITCH + kp] = *reinterpret_cast<uint32_t*>(&pk);
            }
        }
        #pragma unroll
        for (int i = 0; i < 16; i++) {
            int n = wid + 8 * i;
            const float* wp = wt + (size_t)(co0 + n) * K + k0 + 2 * lane;
            __nv_bfloat162 pk = __floats2bfloat162_rn(wp[0], wp[1]);
            ws[n * PITCH + lane] = *reinterpret_cast<uint32_t*>(&pk);
        }
        __syncthreads();

        #pragma unroll
        for (int ks = 0; ks < 4; ks++) {
            int ar = lane >> 2, ac = ks * 8 + (lane & 3);
            uint32_t a[2][4];
            #pragma unroll
            for (int mt = 0; mt < 2; mt++) {
                int r = m0 + mt * 16 + ar;
                a[mt][0] = xs[r * PITCH + ac];
                a[mt][1] = xs[(r + 8) * PITCH + ac];
                a[mt][2] = xs[r * PITCH + ac + 4];
                a[mt][3] = xs[(r + 8) * PITCH + ac + 4];
            }
            #pragma unroll
            for (int nt = 0; nt < 8; nt++) {
                int n = n0 + nt * 8 + ar;
                uint32_t b0 = ws[n * PITCH + ac];
                uint32_t b1 = ws[n * PITCH + ac + 4];
                mma_bf16(acc[0][nt], a[0][0], a[0][1], a[0][2], a[0][3], b0, b1);
                mma_bf16(acc[1][nt], a[1][0], a[1][1], a[1][2], a[1][3], b0, b1);
            }
        }
        __syncthreads();
    }

    #pragma unroll
    for (int nt = 0; nt < 8; nt++) {
        int co = co0 + n0 + nt * 8 + 2 * (lane & 3);
        float bv0 = bias[co], bv1 = bias[co + 1];
        float* o0 = out + (size_t)co * HW + (size_t)h * W;
        float* o1 = out + (size_t)(co + 1) * HW + (size_t)h * W;
        #pragma unroll
        for (int mt = 0; mt < 2; mt++) {
            int px = col0 + m0 + mt * 16 + (lane >> 2);
            o0[px]     = acc[mt][nt][0] + bv0;
            o1[px]     = acc[mt][nt][1] + bv1;
            o0[px + 8] = acc[mt][nt][2] + bv0;
            o1[px + 8] = acc[mt][nt][3] + bv1;
        }
    }
}

// ---------------- scalar 3x3 conv (final 64->3 only) ----------------
template<int CO_TILE>
__global__ void conv3x3_kernel(const float* __restrict__ in, const float* __restrict__ wt,
                               const float* __restrict__ bias, float* __restrict__ out,
                               int Cin, int H, int W) {
    const int TW = 32, TH = 4, PITCH = 35;
    __shared__ float xs[(TH + 2) * PITCH];
    __shared__ float ws[CO_TILE * 9];

    const int nthr = blockDim.x * blockDim.y * blockDim.z;
    const int tid  = threadIdx.x + blockDim.x * (threadIdx.y + blockDim.y * threadIdx.z);
    const int tx = threadIdx.x;
    const int ty = threadIdx.y;
    const int co = blockIdx.z * CO_TILE + threadIdx.z;
    const int w0 = blockIdx.x * TW;
    const int h0 = blockIdx.y * TH;

    float acc[4] = {0.f, 0.f, 0.f, 0.f};

    for (int ci = 0; ci < Cin; ci++) {
        const float* ip = in + (size_t)ci * H * W;
        for (int idx = tid; idx < (TH + 2) * PITCH; idx += nthr) {
            int r = idx / PITCH, c = idx % PITCH;
            float v = 0.f;
            if (c < TW + 2) {
                int gh = h0 + r - 1, gw = w0 + c - 1;
                if (gh >= 0 && gh < H && gw >= 0 && gw < W) v = ip[gh * W + gw];
            }
            xs[idx] = v;
        }
        for (int idx = tid; idx < CO_TILE * 9; idx += nthr) {
            int cc = idx / 9, t = idx % 9;
            ws[idx] = wt[((size_t)(blockIdx.z * CO_TILE + cc) * Cin + ci) * 9 + t];
        }
        __syncthreads();

        float wr[9];
        #pragma unroll
        for (int t = 0; t < 9; t++) wr[t] = ws[threadIdx.z * 9 + t];

        #pragma unroll
        for (int di = 0; di < 3; di++) {
            float xr[6];
            #pragma unroll
            for (int c = 0; c < 6; c++) xr[c] = xs[(ty + di) * PITCH + tx * 4 + c];
            #pragma unroll
            for (int p = 0; p < 4; p++)
                #pragma unroll
                for (int dj = 0; dj < 3; dj++)
                    acc[p] += xr[p + dj] * wr[di * 3 + dj];
        }
        __syncthreads();
    }

    int gh = h0 + ty;
    if (gh < H) {
        float bv = bias[co];
        #pragma unroll
        for (int p = 0; p < 4; p++) {
            int gw = w0 + tx * 4 + p;
            if (gw < W) out[((size_t)co * H + gh) * W + gw] = acc[p] + bv;
        }
    }
}

// ---------------- guide kernel v2: barrier-free, one thread per pixel ----------------
// kk[t][h][w] = exp(-0.5 * sum_c (g_pad[h+di-1][w+dj-1] - g[h][w])^2); center tap == 1.
__global__ __launch_bounds__(128) void kk_kernel(const float* __restrict__ g,
                                                 float* __restrict__ kk,
                                                 int Cg, int H, int W) {
    const int tx = threadIdx.x & 31, ty = threadIdx.x >> 5;
    const int w = blockIdx.x * 32 + tx;
    const int h = blockIdx.y * 4 + ty;
    const size_t HW = (size_t)H * W;

    const bool bl = (w > 0), br = (w < W - 1), bu = (h > 0), bd = (h < H - 1);
    const float* p = g + (size_t)h * W + w;

    float a0 = 0.f, a1 = 0.f, a2 = 0.f, a3 = 0.f,
          a5 = 0.f, a6 = 0.f, a7 = 0.f, a8 = 0.f;

    int c = 0;
    for (; c + 2 <= Cg; c += 2, p += 2 * HW) {
        // channel c
        {
            float ctr = p[0];
            float v0 = (bu && bl) ? p[-W - 1] : 0.f;
            float v1 = bu ? p[-W] : 0.f;
            float v2 = (bu && br) ? p[-W + 1] : 0.f;
            float v3 = bl ? p[-1] : 0.f;
            float v5 = br ? p[1] : 0.f;
            float v6 = (bd && bl) ? p[W - 1] : 0.f;
            float v7 = bd ? p[W] : 0.f;
            float v8 = (bd && br) ? p[W + 1] : 0.f;
            float d0 = v0 - ctr; a0 += d0 * d0;
            float d1 = v1 - ctr; a1 += d1 * d1;
            float d2 = v2 - ctr; a2 += d2 * d2;
            float d3 = v3 - ctr; a3 += d3 * d3;
            float d5 = v5 - ctr; a5 += d5 * d5;
            float d6 = v6 - ctr; a6 += d6 * d6;
            float d7 = v7 - ctr; a7 += d7 * d7;
            float d8 = v8 - ctr; a8 += d8 * d8;
        }
        // channel c+1
        {
            const float* q = p + HW;
            float ctr = q[0];
            float v0 = (bu && bl) ? q[-W - 1] : 0.f;
            float v1 = bu ? q[-W] : 0.f;
            float v2 = (bu && br) ? q[-W + 1] : 0.f;
            float v3 = bl ? q[-1] : 0.f;
            float v5 = br ? q[1] : 0.f;
            float v6 = (bd && bl) ? q[W - 1] : 0.f;
            float v7 = bd ? q[W] : 0.f;
            float v8 = (bd && br) ? q[W + 1] : 0.f;
            float d0 = v0 - ctr; a0 += d0 * d0;
            float d1 = v1 - ctr; a1 += d1 * d1;
            float d2 = v2 - ctr; a2 += d2 * d2;
            float d3 = v3 - ctr; a3 += d3 * d3;
            float d5 = v5 - ctr; a5 += d5 * d5;
            float d6 = v6 - ctr; a6 += d6 * d6;
            float d7 = v7 - ctr; a7 += d7 * d7;
            float d8 = v8 - ctr; a8 += d8 * d8;
        }
    }

    size_t o = (size_t)h * W + w;
    kk[0 * HW + o] = expf(-0.5f * a0);
    kk[1 * HW + o] = expf(-0.5f * a1);
    kk[2 * HW + o] = expf(-0.5f * a2);
    kk[3 * HW + o] = expf(-0.5f * a3);
    kk[4 * HW + o] = 1.0f;
    kk[5 * HW + o] = expf(-0.5f * a5);
    kk[6 * HW + o] = expf(-0.5f * a6);
    kk[7 * HW + o] = expf(-0.5f * a7);
    kk[8 * HW + o] = expf(-0.5f * a8);
}

// ---------------- PAC transposed conv (stride 2, parity-sparse), CI_TILE=4 ----------------
__global__ __launch_bounds__(256) void pac_kernel(
    const float* __restrict__ x, const float* __restrict__ kk,
    const float* __restrict__ wt, const float* __restrict__ bias,
    float* __restrict__ out, int Cin, int Cout, int H, int W)
{
    __shared__ float xs[4][9 * 36];
    __shared__ float ws[4][4 * 12];
    const int tid = threadIdx.x;
    const int tx = tid & 7, ty = (tid >> 3) & 7, tz = tid >> 6;
    const int s0 = blockIdx.x * 32, r0 = blockIdx.y * 8;
    const int coBase = blockIdx.z * 4;
    const int co = coBase + tz;

    float acc[4][9];
    #pragma unroll
    for (int q = 0; q < 4; q++)
        #pragma unroll
        for (int p = 0; p < 9; p++) acc[q][p] = 0.f;

    for (int cb = 0; cb < Cin; cb += 4) {
        #pragma unroll
        for (int ci4 = 0; ci4 < 4; ci4++) {
            const float* ip = x + (size_t)(cb + ci4) * H * W;
            for (int idx = tid; idx < 9 * 33; idx += 256) {
                int r = idx / 33, c = idx - r * 33;
                int gr = r0 + r, gc = s0 + c;
                xs[ci4][r * 36 + c] = (gr < H && gc < W) ? ip[gr * W + gc] : 0.f;
            }
        }
        if (tid < 144) {
            int ci4 = tid / 36, rem = tid - ci4 * 36, cc = rem / 9, t = rem - cc * 9;
            ws[ci4][cc * 12 + t] = wt[((size_t)(cb + ci4) * Cout + coBase + cc) * 9 + t];
        }
        __syncthreads();

        #pragma unroll
        for (int ci4 = 0; ci4 < 4; ci4++) {
            float4 w0v = *(const float4*)&ws[ci4][tz * 12];
            float4 w1v = *(const float4*)&ws[ci4][tz * 12 + 4];
            float  w8  = ws[ci4][tz * 12 + 8];
            float wr[9] = {w0v.x, w0v.y, w0v.z, w0v.w, w1v.x, w1v.y, w1v.z, w1v.w, w8};
            float4 a4 = *(const float4*)&xs[ci4][ty * 36 + tx * 4];
            float  a5 = xs[ci4][ty * 36 + tx * 4 + 4];
            float4 b4 = *(const float4*)&xs[ci4][(ty + 1) * 36 + tx * 4];
            float  b5 = xs[ci4][(ty + 1) * 36 + tx * 4 + 4];
            float xa[5] = {a4.x, a4.y, a4.z, a4.w, a5};
            float xb[5] = {b4.x, b4.y, b4.z, b4.w, b5};
            #pragma unroll
            for (int q = 0; q < 4; q++) {
                float x00 = xa[q], x01 = xa[q + 1], x10 = xb[q], x11 = xb[q + 1];
                acc[q][0] += x00 * wr[4];
                acc[q][1] += x00 * wr[3];
                acc[q][2] += x01 * wr[5];
                acc[q][3] += x00 * wr[1];
                acc[q][4] += x10 * wr[7];
                acc[q][5] += x00 * wr[0];
                acc[q][6] += x01 * wr[2];
                acc[q][7] += x10 * wr[6];
                acc[q][8] += x11 * wr[8];
            }
        }
        __syncthreads();
    }

    const int Ho = 2 * H, Wo = 2 * W;
    const size_t HW = (size_t)Ho * Wo;
    float bv = bias[co];
    int r = r0 + ty;
    float* op = out + (size_t)co * HW;
    #pragma unroll
    for (int q = 0; q < 4; q++) {
        int s = s0 + tx * 4 + q;
        size_t b00 = (size_t)(2 * r) * Wo + 2 * s;
        size_t b10 = b00 + Wo;
        float o00 = bv + kk[4 * HW + b00] * acc[q][0];
        float o01 = bv + kk[3 * HW + b00 + 1] * acc[q][1]
                       + kk[5 * HW + b00 + 1] * acc[q][2];
        float o10 = bv + kk[1 * HW + b10] * acc[q][3]
                       + kk[7 * HW + b10] * acc[q][4];
        float o11 = bv + kk[0 * HW + b10 + 1] * acc[q][5]
                       + kk[2 * HW + b10 + 1] * acc[q][6]
                       + kk[6 * HW + b10 + 1] * acc[q][7]
                       + kk[8 * HW + b10 + 1] * acc[q][8];
        op[b00] = o00; op[b00 + 1] = o01;
        op[b10] = o10; op[b10 + 1] = o11;
    }
}

// ---------------- launch ----------------
extern "C" void kernel_launch(void* const* d_in, const int* in_sizes, int n_in,
                              void* d_out, int out_size) {
    const float* x       = (const float*)d_in[0];
    const float* ef_lv2  = (const float*)d_in[1];
    const float* ef_lv1  = (const float*)d_in[2];
    const float* w_adj2  = (const float*)d_in[3];
    const float* b_adj2  = (const float*)d_in[4];
    const float* w_adj1  = (const float*)d_in[5];
    const float* b_adj1  = (const float*)d_in[6];
    const float* w_pac16 = (const float*)d_in[7];
    const float* b_pac16 = (const float*)d_in[8];
    const float* w_pac20 = (const float*)d_in[9];
    const float* b_pac20 = (const float*)d_in[10];
    const float* w_out   = (const float*)d_in[11];
    const float* b_out   = (const float*)d_in[12];
    float* outp = (float*)d_out;

    float *xA, *g2, *kk1, *xB, *g1, *kk2, *xC;
    cudaGetSymbolAddress((void**)&xA,  g_xA);
    cudaGetSymbolAddress((void**)&g2,  g_g2);
    cudaGetSymbolAddress((void**)&kk1, g_kk1);
    cudaGetSymbolAddress((void**)&xB,  g_xB);
    cudaGetSymbolAddress((void**)&g1,  g_g1);
    cudaGetSymbolAddress((void**)&kk2, g_kk2);
    cudaGetSymbolAddress((void**)&xC,  g_xC);

    // stage 1: collapsed double inorm-residual (256, 64, 64)
    dinorm_kernel<<<256, 256>>>(x, xA, 64 * 64);

    // g2 = conv3x3(ef_lv2; 128->256 @128x128): K = 1152, both N-halves in one launch
    conv_mma_kernel<<<dim3(1, 128, 2), 256>>>(ef_lv2, w_adj2, b_adj2, g2, 128, 128, 128);

    // kk1 from g2 (barrier-free)
    kk_kernel<<<dim3(4, 32), 128>>>(g2, kk1, 256, 128, 128);

    // pac1: (256,64,64) -> (128,128,128)
    pac_kernel<<<dim3(2, 8, 32), 256>>>(xA, kk1, w_pac16, b_pac16, xB, 256, 128, 64, 64);

    dinorm_kernel<<<128, 256>>>(xB, xB, 128 * 128);

    // g1 = conv3x3(ef_lv1; 64->128 @256x256): K = 576
    conv_mma_kernel<<<dim3(2, 256, 1), 256>>>(ef_lv1, w_adj1, b_adj1, g1, 64, 256, 256);

    // kk2 from g1 (barrier-free)
    kk_kernel<<<dim3(8, 64), 128>>>(g1, kk2, 128, 256, 256);

    // pac2: (128,128,128) -> (64,256,256)
    pac_kernel<<<dim3(4, 16, 16), 256>>>(xB, kk2, w_pac20, b_pac20, xC, 128, 64, 128, 128);

    dinorm_kernel<<<64, 256>>>(xC, xC, 256 * 256);

    // final conv: 64->3 @256x256 (scalar fp32, precision-critical path)
    conv3x3_kernel<3><<<dim3(8, 64, 1), dim3(8, 4, 3)>>>(xC, w_out, b_out, outp, 64, 256, 256);
}

// round 10
// speedup vs baseline: 3.8649x; 1.8059x over previous
#include <cuda_runtime.h>
#include <cuda_bf16.h>
#include <math.h>
#include <cstdint>

#define EPS 1e-5f

// ---------------- scratch (static device globals) ----------------
__device__ float g_xA [256*64*64];
__device__ float g_g2 [256*128*128];
__device__ float g_kk1[9*128*128];
__device__ float g_xB [128*128*128];
__device__ float g_g1 [128*256*256];
__device__ float g_kk2[9*256*256];
__device__ float g_xC [64*256*256];
__device__ float g_G  [9437184];       // pac GEMM output, max 576*16384 floats (36 MB)

// ---------------- double instance-norm residual ----------------
__global__ void dinorm_kernel(const float* __restrict__ in, float* __restrict__ out, int N) {
    const int c = blockIdx.x;
    const float* x = in + (size_t)c * N;
    float* y = out + (size_t)c * N;

    float s = 0.f, s2 = 0.f;
    for (int i = threadIdx.x; i < N; i += blockDim.x) {
        float v = x[i];
        s += v; s2 += v * v;
    }
    #pragma unroll
    for (int o = 16; o > 0; o >>= 1) {
        s  += __shfl_down_sync(0xffffffffu, s,  o);
        s2 += __shfl_down_sync(0xffffffffu, s2, o);
    }
    __shared__ float redA[8], redB[8];
    __shared__ float s_m, s_scale;
    int wid = threadIdx.x >> 5, lid = threadIdx.x & 31;
    if (lid == 0) { redA[wid] = s; redB[wid] = s2; }
    __syncthreads();
    if (threadIdx.x == 0) {
        float S = 0.f, S2 = 0.f;
        int nw = blockDim.x >> 5;
        for (int i = 0; i < nw; i++) { S += redA[i]; S2 += redB[i]; }
        float m = S / N;
        float v = S2 / N - m * m;
        if (v < 0.f) v = 0.f;
        float r  = rsqrtf(v + EPS);
        float r2 = rsqrtf(v * (1.f + r) * (1.f + r) + EPS);
        s_m = m; s_scale = (1.f + r) * (1.f + r2);
    }
    __syncthreads();
    float m = s_m, sc = s_scale;
    for (int i = threadIdx.x; i < N; i += blockDim.x) {
        float v = x[i];
        y[i] = (v - m) * sc + m;
    }
}

// ---------------- bf16 mma helper ----------------
__device__ __forceinline__ void mma_bf16(float* c, uint32_t a0, uint32_t a1,
                                         uint32_t a2, uint32_t a3,
                                         uint32_t b0, uint32_t b1) {
    asm volatile(
        "mma.sync.aligned.m16n8k16.row.col.f32.bf16.bf16.f32 "
        "{%0,%1,%2,%3}, {%4,%5,%6,%7}, {%8,%9}, {%0,%1,%2,%3};"
        : "+f"(c[0]), "+f"(c[1]), "+f"(c[2]), "+f"(c[3])
        : "r"(a0), "r"(a1), "r"(a2), "r"(a3), "r"(b0), "r"(b1));
}

__device__ __forceinline__ uint32_t pack_bf16(float a, float b) {
    __nv_bfloat162 p = __floats2bfloat162_rn(a, b);
    return *reinterpret_cast<uint32_t*>(&p);
}

// ---------------- bf16 mma.sync implicit-GEMM 3x3 SAME conv (guide path) ----------------
__global__ __launch_bounds__(256) void conv_mma_kernel(
    const float* __restrict__ in, const float* __restrict__ wt,
    const float* __restrict__ bias, float* __restrict__ out,
    int Cin, int H, int W)
{
    const int PITCH = 36;
    __shared__ uint32_t xs[128 * PITCH];
    __shared__ uint32_t ws[128 * PITCH];

    const int tid = threadIdx.x, wid = tid >> 5, lane = tid & 31;
    const int h = blockIdx.y, col0 = blockIdx.x * 128;
    const int co0 = blockIdx.z * 128;
    const size_t HW = (size_t)H * W;
    const int K = Cin * 9;
    const int nch = K / 64;

    const int wm = wid & 3, wn = wid >> 2;
    const int m0 = wm * 32, n0 = wn * 64;

    float acc[2][8][4];
    #pragma unroll
    for (int mt = 0; mt < 2; mt++)
        #pragma unroll
        for (int nt = 0; nt < 8; nt++)
            #pragma unroll
            for (int r = 0; r < 4; r++) acc[mt][nt][r] = 0.f;

    for (int ch = 0; ch < nch; ch++) {
        const int k0 = ch * 64;

        #pragma unroll
        for (int e = 0; e < 4; e++) {
            int kp = wid * 4 + e;
            int k  = k0 + kp * 2;
            int ci0 = k / 9, t0 = k - ci0 * 9;
            int di0 = t0 / 3, dj0 = t0 - di0 * 3;
            int k1 = k + 1;
            int ci1 = k1 / 9, t1 = k1 - ci1 * 9;
            int di1 = t1 / 3, dj1 = t1 - di1 * 3;
            int gh0 = h + di0 - 1, gh1 = h + di1 - 1;
            bool ok0 = (gh0 >= 0 && gh0 < H), ok1 = (gh1 >= 0 && gh1 < H);
            const float* ip0 = in + (size_t)ci0 * HW + (size_t)gh0 * W;
            const float* ip1 = in + (size_t)ci1 * HW + (size_t)gh1 * W;
            #pragma unroll
            for (int p4 = 0; p4 < 4; p4++) {
                int px = p4 * 32 + lane;
                int gw0 = col0 + px + dj0 - 1;
                int gw1 = col0 + px + dj1 - 1;
                float v0 = (ok0 && gw0 >= 0 && gw0 < W) ? ip0[gw0] : 0.f;
                float v1 = (ok1 && gw1 >= 0 && gw1 < W) ? ip1[gw1] : 0.f;
                xs[px * PITCH + kp] = pack_bf16(v0, v1);
            }
        }
        #pragma unroll
        for (int i = 0; i < 16; i++) {
            int n = wid + 8 * i;
            const float* wp = wt + (size_t)(co0 + n) * K + k0 + 2 * lane;
            ws[n * PITCH + lane] = pack_bf16(wp[0], wp[1]);
        }
        __syncthreads();

        #pragma unroll
        for (int ks = 0; ks < 4; ks++) {
            int ar = lane >> 2, ac = ks * 8 + (lane & 3);
            uint32_t a[2][4];
            #pragma unroll
            for (int mt = 0; mt < 2; mt++) {
                int r = m0 + mt * 16 + ar;
                a[mt][0] = xs[r * PITCH + ac];
                a[mt][1] = xs[(r + 8) * PITCH + ac];
                a[mt][2] = xs[r * PITCH + ac + 4];
                a[mt][3] = xs[(r + 8) * PITCH + ac + 4];
            }
            #pragma unroll
            for (int nt = 0; nt < 8; nt++) {
                int n = n0 + nt * 8 + ar;
                uint32_t b0 = ws[n * PITCH + ac];
                uint32_t b1 = ws[n * PITCH + ac + 4];
                mma_bf16(acc[0][nt], a[0][0], a[0][1], a[0][2], a[0][3], b0, b1);
                mma_bf16(acc[1][nt], a[1][0], a[1][1], a[1][2], a[1][3], b0, b1);
            }
        }
        __syncthreads();
    }

    #pragma unroll
    for (int nt = 0; nt < 8; nt++) {
        int co = co0 + n0 + nt * 8 + 2 * (lane & 3);
        float bv0 = bias[co], bv1 = bias[co + 1];
        float* o0 = out + (size_t)co * HW + (size_t)h * W;
        float* o1 = out + (size_t)(co + 1) * HW + (size_t)h * W;
        #pragma unroll
        for (int mt = 0; mt < 2; mt++) {
            int px = col0 + m0 + mt * 16 + (lane >> 2);
            o0[px]     = acc[mt][nt][0] + bv0;
            o1[px]     = acc[mt][nt][1] + bv1;
            o0[px + 8] = acc[mt][nt][2] + bv0;
            o1[px + 8] = acc[mt][nt][3] + bv1;
        }
    }
}

// ---------------- split-bf16 GEMM for PAC:  G[n][px] = sum_k x[k][px] * wt[k][n] ----------------
// x: (Cin, M) planes;  wt: (Cin, N) row-major (= (Cin,Cout,3,3));  G: (N, M).
// acc = xh*wh + xh*wl + xl*wh in fp32 -> rel err ~1.6e-5.
__global__ __launch_bounds__(256) void pac_gemm_kernel(
    const float* __restrict__ x, const float* __restrict__ wt,
    float* __restrict__ G, int Cin, int N, int M)
{
    const int P = 37;                    // stage stores conflict-free; frag loads ~2-way worst
    extern __shared__ uint32_t sm[];
    uint32_t* ah = sm;
    uint32_t* al = ah + 128 * P;
    uint32_t* bh = al + 128 * P;
    uint32_t* bl = bh + 128 * P;

    const int tid = threadIdx.x, wid = tid >> 5, lane = tid & 31;
    const int px0 = blockIdx.x * 128, n0 = blockIdx.y * 128;
    const int wm = wid & 3, wn = wid >> 2;
    const int m0 = wm * 32, nb0 = wn * 64;
    const int nch = Cin / 64;

    float acc[2][8][4];
    #pragma unroll
    for (int mt = 0; mt < 2; mt++)
        #pragma unroll
        for (int nt = 0; nt < 8; nt++)
            #pragma unroll
            for (int r = 0; r < 4; r++) acc[mt][nt][r] = 0.f;

    for (int ch = 0; ch < nch; ch++) {
        const int k0 = ch * 64;

        // stage A: [px][kpair], hi/lo split
        #pragma unroll
        for (int i = 0; i < 16; i++) {
            int idx = tid + 256 * i;
            int px = idx & 127, kp = idx >> 7;
            const float* xp = x + (size_t)(k0 + 2 * kp) * M + px0 + px;
            float v0 = xp[0], v1 = xp[M];
            float h0 = __bfloat162float(__float2bfloat16_rn(v0));
            float h1 = __bfloat162float(__float2bfloat16_rn(v1));
            ah[px * P + kp] = pack_bf16(h0, h1);
            al[px * P + kp] = pack_bf16(v0 - h0, v1 - h1);
        }
        // stage B: [n][kpair], hi/lo split (guard n >= N with zeros)
        #pragma unroll
        for (int i = 0; i < 16; i++) {
            int idx = tid + 256 * i;
            int n = idx & 127, kp = idx >> 7;
            int gn = n0 + n;
            float v0 = 0.f, v1 = 0.f;
            if (gn < N) {
                const float* wp = wt + (size_t)(k0 + 2 * kp) * N + gn;
                v0 = wp[0]; v1 = wp[N];
            }
            float h0 = __bfloat162float(__float2bfloat16_rn(v0));
            float h1 = __bfloat162float(__float2bfloat16_rn(v1));
            bh[n * P + kp] = pack_bf16(h0, h1);
            bl[n * P + kp] = pack_bf16(v0 - h0, v1 - h1);
        }
        __syncthreads();

        #pragma unroll
        for (int ks = 0; ks < 4; ks++) {
            int ar = lane >> 2, ac = ks * 8 + (lane & 3);
            uint32_t Ah[2][4], Al[2][4];
            #pragma unroll
            for (int mt = 0; mt < 2; mt++) {
                int r = m0 + mt * 16 + ar;
                Ah[mt][0] = ah[r * P + ac];
                Ah[mt][1] = ah[(r + 8) * P + ac];
                Ah[mt][2] = ah[r * P + ac + 4];
                Ah[mt][3] = ah[(r + 8) * P + ac + 4];
                Al[mt][0] = al[r * P + ac];
                Al[mt][1] = al[(r + 8) * P + ac];
                Al[mt][2] = al[r * P + ac + 4];
                Al[mt][3] = al[(r + 8) * P + ac + 4];
            }
            #pragma unroll
            for (int nt = 0; nt < 8; nt++) {
                int n = nb0 + nt * 8 + ar;
                uint32_t bh0 = bh[n * P + ac], bh1 = bh[n * P + ac + 4];
                uint32_t bl0 = bl[n * P + ac], bl1 = bl[n * P + ac + 4];
                mma_bf16(acc[0][nt], Ah[0][0], Ah[0][1], Ah[0][2], Ah[0][3], bh0, bh1);
                mma_bf16(acc[1][nt], Ah[1][0], Ah[1][1], Ah[1][2], Ah[1][3], bh0, bh1);
                mma_bf16(acc[0][nt], Ah[0][0], Ah[0][1], Ah[0][2], Ah[0][3], bl0, bl1);
                mma_bf16(acc[1][nt], Ah[1][0], Ah[1][1], Ah[1][2], Ah[1][3], bl0, bl1);
                mma_bf16(acc[0][nt], Al[0][0], Al[0][1], Al[0][2], Al[0][3], bh0, bh1);
                mma_bf16(acc[1][nt], Al[1][0], Al[1][1], Al[1][2], Al[1][3], bh0, bh1);
            }
        }
        __syncthreads();
    }

    #pragma unroll
    for (int nt = 0; nt < 8; nt++) {
        int n = n0 + nb0 + nt * 8 + 2 * (lane & 3);
        #pragma unroll
        for (int mt = 0; mt < 2; mt++) {
            int px = px0 + m0 + mt * 16 + (lane >> 2);
            if (n < N) {
                G[(size_t)n * M + px]     = acc[mt][nt][0];
                G[(size_t)n * M + px + 8] = acc[mt][nt][2];
            }
            if (n + 1 < N) {
                G[(size_t)(n + 1) * M + px]     = acc[mt][nt][1];
                G[(size_t)(n + 1) * M + px + 8] = acc[mt][nt][3];
            }
        }
    }
}

// ---------------- PAC apply: gather G planes through kk into the upsampled output ----------------
// out(2r,2s)     = b + kk4*G[4][r,s]
// out(2r,2s+1)   = b + kk3*G[3][r,s] + kk5*G[5][r,s+1]
// out(2r+1,2s)   = b + kk1*G[1][r,s] + kk7*G[7][r+1,s]
// out(2r+1,2s+1) = b + kk0*G[0][r,s] + kk2*G[2][r,s+1] + kk6*G[6][r+1,s] + kk8*G[8][r+1,s+1]
__global__ __launch_bounds__(128) void pac_apply_kernel(
    const float* __restrict__ G, const float* __restrict__ kk,
    const float* __restrict__ bias, float* __restrict__ out,
    int H, int W)   // input dims
{
    const int s = blockIdx.x * 32 + (threadIdx.x & 31);
    const int r = blockIdx.y * 4 + (threadIdx.x >> 5);
    const int co = blockIdx.z;
    const size_t M = (size_t)H * W;
    const size_t base = (size_t)r * W + s;
    const float* gp = G + (size_t)co * 9 * M;
    const bool sr = (s + 1 < W), rd = (r + 1 < H);
    const int Wo = 2 * W;
    const size_t HWo = 4 * M;
    const size_t b00 = (size_t)(2 * r) * Wo + 2 * s;
    const size_t b10 = b00 + Wo;
    const float bv = bias[co];

    float o00 = bv + kk[4 * HWo + b00] * gp[4 * M + base];
    float o01 = bv + kk[3 * HWo + b00 + 1] * gp[3 * M + base]
              + (sr ? kk[5 * HWo + b00 + 1] * gp[5 * M + base + 1] : 0.f);
    float o10 = bv + kk[1 * HWo + b10] * gp[1 * M + base]
              + (rd ? kk[7 * HWo + b10] * gp[7 * M + base + W] : 0.f);
    float o11 = bv + kk[0 * HWo + b10 + 1] * gp[0 * M + base]
              + (sr ? kk[2 * HWo + b10 + 1] * gp[2 * M + base + 1] : 0.f)
              + (rd ? kk[6 * HWo + b10 + 1] * gp[6 * M + base + W] : 0.f)
              + ((sr && rd) ? kk[8 * HWo + b10 + 1] * gp[8 * M + base + W + 1] : 0.f);

    float* op = out + (size_t)co * HWo;
    op[b00] = o00; op[b00 + 1] = o01;
    op[b10] = o10; op[b10 + 1] = o11;
}

// ---------------- scalar 3x3 conv (final 64->3 only) ----------------
template<int CO_TILE>
__global__ void conv3x3_kernel(const float* __restrict__ in, const float* __restrict__ wt,
                               const float* __restrict__ bias, float* __restrict__ out,
                               int Cin, int H, int W) {
    const int TW = 32, TH = 4, PITCH = 35;
    __shared__ float xs[(TH + 2) * PITCH];
    __shared__ float ws[CO_TILE * 9];

    const int nthr = blockDim.x * blockDim.y * blockDim.z;
    const int tid  = threadIdx.x + blockDim.x * (threadIdx.y + blockDim.y * threadIdx.z);
    const int tx = threadIdx.x;
    const int ty = threadIdx.y;
    const int co = blockIdx.z * CO_TILE + threadIdx.z;
    const int w0 = blockIdx.x * TW;
    const int h0 = blockIdx.y * TH;

    float acc[4] = {0.f, 0.f, 0.f, 0.f};

    for (int ci = 0; ci < Cin; ci++) {
        const float* ip = in + (size_t)ci * H * W;
        for (int idx = tid; idx < (TH + 2) * PITCH; idx += nthr) {
            int r = idx / PITCH, c = idx % PITCH;
            float v = 0.f;
            if (c < TW + 2) {
                int gh = h0 + r - 1, gw = w0 + c - 1;
                if (gh >= 0 && gh < H && gw >= 0 && gw < W) v = ip[gh * W + gw];
            }
            xs[idx] = v;
        }
        for (int idx = tid; idx < CO_TILE * 9; idx += nthr) {
            int cc = idx / 9, t = idx % 9;
            ws[idx] = wt[((size_t)(blockIdx.z * CO_TILE + cc) * Cin + ci) * 9 + t];
        }
        __syncthreads();

        float wr[9];
        #pragma unroll
        for (int t = 0; t < 9; t++) wr[t] = ws[threadIdx.z * 9 + t];

        #pragma unroll
        for (int di = 0; di < 3; di++) {
            float xr[6];
            #pragma unroll
            for (int c = 0; c < 6; c++) xr[c] = xs[(ty + di) * PITCH + tx * 4 + c];
            #pragma unroll
            for (int p = 0; p < 4; p++)
                #pragma unroll
                for (int dj = 0; dj < 3; dj++)
                    acc[p] += xr[p + dj] * wr[di * 3 + dj];
        }
        __syncthreads();
    }

    int gh = h0 + ty;
    if (gh < H) {
        float bv = bias[co];
        #pragma unroll
        for (int p = 0; p < 4; p++) {
            int gw = w0 + tx * 4 + p;
            if (gw < W) out[((size_t)co * H + gh) * W + gw] = acc[p] + bv;
        }
    }
}

// ---------------- guide kernel: barrier-free, one thread per pixel ----------------
__global__ __launch_bounds__(128) void kk_kernel(const float* __restrict__ g,
                                                 float* __restrict__ kk,
                                                 int Cg, int H, int W) {
    const int tx = threadIdx.x & 31, ty = threadIdx.x >> 5;
    const int w = blockIdx.x * 32 + tx;
    const int h = blockIdx.y * 4 + ty;
    const size_t HW = (size_t)H * W;

    const bool bl = (w > 0), br = (w < W - 1), bu = (h > 0), bd = (h < H - 1);
    const float* p = g + (size_t)h * W + w;

    float a0 = 0.f, a1 = 0.f, a2 = 0.f, a3 = 0.f,
          a5 = 0.f, a6 = 0.f, a7 = 0.f, a8 = 0.f;

    for (int c = 0; c + 2 <= Cg; c += 2, p += 2 * HW) {
        {
            float ctr = p[0];
            float v0 = (bu && bl) ? p[-W - 1] : 0.f;
            float v1 = bu ? p[-W] : 0.f;
            float v2 = (bu && br) ? p[-W + 1] : 0.f;
            float v3 = bl ? p[-1] : 0.f;
            float v5 = br ? p[1] : 0.f;
            float v6 = (bd && bl) ? p[W - 1] : 0.f;
            float v7 = bd ? p[W] : 0.f;
            float v8 = (bd && br) ? p[W + 1] : 0.f;
            float d0 = v0 - ctr; a0 += d0 * d0;
            float d1 = v1 - ctr; a1 += d1 * d1;
            float d2 = v2 - ctr; a2 += d2 * d2;
            float d3 = v3 - ctr; a3 += d3 * d3;
            float d5 = v5 - ctr; a5 += d5 * d5;
            float d6 = v6 - ctr; a6 += d6 * d6;
            float d7 = v7 - ctr; a7 += d7 * d7;
            float d8 = v8 - ctr; a8 += d8 * d8;
        }
        {
            const float* q = p + HW;
            float ctr = q[0];
            float v0 = (bu && bl) ? q[-W - 1] : 0.f;
            float v1 = bu ? q[-W] : 0.f;
            float v2 = (bu && br) ? q[-W + 1] : 0.f;
            float v3 = bl ? q[-1] : 0.f;
            float v5 = br ? q[1] : 0.f;
            float v6 = (bd && bl) ? q[W - 1] : 0.f;
            float v7 = bd ? q[W] : 0.f;
            float v8 = (bd && br) ? q[W + 1] : 0.f;
            float d0 = v0 - ctr; a0 += d0 * d0;
            float d1 = v1 - ctr; a1 += d1 * d1;
            float d2 = v2 - ctr; a2 += d2 * d2;
            float d3 = v3 - ctr; a3 += d3 * d3;
            float d5 = v5 - ctr; a5 += d5 * d5;
            float d6 = v6 - ctr; a6 += d6 * d6;
            float d7 = v7 - ctr; a7 += d7 * d7;
            float d8 = v8 - ctr; a8 += d8 * d8;
        }
    }

    size_t o = (size_t)h * W + w;
    kk[0 * HW + o] = expf(-0.5f * a0);
    kk[1 * HW + o] = expf(-0.5f * a1);
    kk[2 * HW + o] = expf(-0.5f * a2);
    kk[3 * HW + o] = expf(-0.5f * a3);
    kk[4 * HW + o] = 1.0f;
    kk[5 * HW + o] = expf(-0.5f * a5);
    kk[6 * HW + o] = expf(-0.5f * a6);
    kk[7 * HW + o] = expf(-0.5f * a7);
    kk[8 * HW + o] = expf(-0.5f * a8);
}

// ---------------- launch ----------------
extern "C" void kernel_launch(void* const* d_in, const int* in_sizes, int n_in,
                              void* d_out, int out_size) {
    const float* x       = (const float*)d_in[0];
    const float* ef_lv2  = (const float*)d_in[1];
    const float* ef_lv1  = (const float*)d_in[2];
    const float* w_adj2  = (const float*)d_in[3];
    const float* b_adj2  = (const float*)d_in[4];
    const float* w_adj1  = (const float*)d_in[5];
    const float* b_adj1  = (const float*)d_in[6];
    const float* w_pac16 = (const float*)d_in[7];
    const float* b_pac16 = (const float*)d_in[8];
    const float* w_pac20 = (const float*)d_in[9];
    const float* b_pac20 = (const float*)d_in[10];
    const float* w_out   = (const float*)d_in[11];
    const float* b_out   = (const float*)d_in[12];
    float* outp = (float*)d_out;

    float *xA, *g2, *kk1, *xB, *g1, *kk2, *xC, *G;
    cudaGetSymbolAddress((void**)&xA,  g_xA);
    cudaGetSymbolAddress((void**)&g2,  g_g2);
    cudaGetSymbolAddress((void**)&kk1, g_kk1);
    cudaGetSymbolAddress((void**)&xB,  g_xB);
    cudaGetSymbolAddress((void**)&g1,  g_g1);
    cudaGetSymbolAddress((void**)&kk2, g_kk2);
    cudaGetSymbolAddress((void**)&xC,  g_xC);
    cudaGetSymbolAddress((void**)&G,   g_G);

    const int SMEM_PG = 4 * 128 * 37 * 4;   // 75776 B
    cudaFuncSetAttribute(pac_gemm_kernel, cudaFuncAttributeMaxDynamicSharedMemorySize, SMEM_PG);

    // stage 1: collapsed double inorm-residual (256, 64, 64)
    dinorm_kernel<<<256, 256>>>(x, xA, 64 * 64);

    // g2 = conv3x3(ef_lv2; 128->256 @128x128)
    conv_mma_kernel<<<dim3(1, 128, 2), 256>>>(ef_lv2, w_adj2, b_adj2, g2, 128, 128, 128);

    // kk1 from g2
    kk_kernel<<<dim3(4, 32), 128>>>(g2, kk1, 256, 128, 128);

    // pac1: GEMM (M=4096, N=1152, K=256) + apply -> xB (128,128,128)
    pac_gemm_kernel<<<dim3(32, 9), 256, SMEM_PG>>>(xA, w_pac16, G, 256, 1152, 4096);
    pac_apply_kernel<<<dim3(2, 16, 128), 128>>>(G, kk1, b_pac16, xB, 64, 64);

    dinorm_kernel<<<128, 256>>>(xB, xB, 128 * 128);

    // g1 = conv3x3(ef_lv1; 64->128 @256x256)
    conv_mma_kernel<<<dim3(2, 256, 1), 256>>>(ef_lv1, w_adj1, b_adj1, g1, 64, 256, 256);

    // kk2 from g1
    kk_kernel<<<dim3(8, 64), 128>>>(g1, kk2, 128, 256, 256);

    // pac2: GEMM (M=16384, N=576, K=128) + apply -> xC (64,256,256)
    pac_gemm_kernel<<<dim3(128, 5), 256, SMEM_PG>>>(xB, w_pac20, G, 128, 576, 16384);
    pac_apply_kernel<<<dim3(4, 32, 64), 128>>>(G, kk2, b_pac20, xC, 128, 128);

    dinorm_kernel<<<64, 256>>>(xC, xC, 256 * 256);

    // final conv: 64->3 @256x256 (scalar fp32, precision-critical path)
    conv3x3_kernel<3><<<dim3(8, 64, 1), dim3(8, 4, 3)>>>(xC, w_out, b_out, outp, 64, 256, 256);
}